// round 5
// baseline (speedup 1.0000x reference)
#include <cuda_runtime.h>
#include <cuda_bf16.h>
#include <math.h>
#include <stdint.h>

// ---------------- problem constants ----------------
#define NROWS (32*64*64)          // 131072 rows, dim 64
#define D 64
#define KCODES 512
#define TM 128                    // rows per CTA
#define NBLK (NROWS/TM)           // 1024
#define THREADS 256
#define MARGIN 0.12f              // >>2x bf16 input-rounding bound on 2*dot
#define CAP 8

#define OUT_ELEMS ((size_t)NROWS*(size_t)D)
#define DIFF_OFF  (OUT_ELEMS)
#define IND_OFF   (OUT_ELEMS + 1)
#define PPL_OFF   (OUT_ELEMS + 1 + (size_t)NROWS)

// ---------------- device scratch (no cudaMalloc) ----------------
__device__ float g_en[KCODES];                    // ||e_k||^2, XLA rounding order
__device__ float g_eT[KCODES*D];                  // fp32 codebook [K][D]
// fragment-ordered bf16 codebook: 64 tiles x 32 lanes x 12 words (8 used + pad)
__device__ __align__(16) uint32_t g_frag[64*32*12];
__device__ float g_partial[NBLK];

// ---------------- helpers ----------------
__device__ __forceinline__ uint32_t packbf2(float a, float b) {
    __nv_bfloat162 v = __float22bfloat162_rn(make_float2(a, b)); // .x -> low half
    return *(uint32_t*)&v;
}
__device__ __forceinline__ void mma16816(float* c, const uint32_t* a, uint32_t b0, uint32_t b1) {
    asm volatile("mma.sync.aligned.m16n8k16.row.col.f32.bf16.bf16.f32 "
        "{%0,%1,%2,%3}, {%4,%5,%6,%7}, {%8,%9}, {%0,%1,%2,%3};"
        : "+f"(c[0]), "+f"(c[1]), "+f"(c[2]), "+f"(c[3])
        : "r"(a[0]), "r"(a[1]), "r"(a[2]), "r"(a[3]), "r"(b0), "r"(b1));
}
// exact distance in the reference rounding chain
__device__ __forceinline__ float exact_dist(const float* __restrict__ xrow,
                                            const float* __restrict__ e,
                                            float fn, float en) {
    float dot = 0.f;
#pragma unroll
    for (int q = 0; q < 16; q++) {
        float4 ev = __ldg((const float4*)e + q);
        float4 xv = __ldg((const float4*)xrow + q);
        dot = __fmaf_rn(xv.x, ev.x, dot);
        dot = __fmaf_rn(xv.y, ev.y, dot);
        dot = __fmaf_rn(xv.z, ev.z, dot);
        dot = __fmaf_rn(xv.w, ev.w, dot);
    }
    return __fadd_rn(__fsub_rn(fn, __fadd_rn(dot, dot)), en);
}

// smem layout (dynamic)
#define OFF_B    0                     // 98304 B : fragment codebook
#define OFF_ENS  98304                 // 2048  B : en[512]
#define OFF_FN   100352                // 512   B : fn[128]
#define OFF_BK   100864                // 512   B : bestk[128]
#define OFF_RED  101376                // 1024  B : MSE reduce
#define SMEM_TOTAL 102400

// ---------------------------------------------------------------------------
// Prep: 4 blocks x 256. Block nt owns codes [nt*128, +128) == tiles nt*16..+16.
// Produces g_en (XLA rounding), g_eT fp32, g_frag (HMMA B-fragment order).
// ---------------------------------------------------------------------------
#define PK 128
__global__ void vq_prep(const float* __restrict__ embed) {
    __shared__ float tile[D * PK];   // tile[d*PK + kl]
    const int tid = threadIdx.x;
    const int nt  = blockIdx.x;
    const int k0  = nt * PK;

    for (int i = tid; i < D * PK / 4; i += THREADS) {
        int d  = i / (PK/4);
        int kq = i % (PK/4);
        ((float4*)tile)[i] = __ldg((const float4*)(embed + d*KCODES + k0) + kq);
    }
    __syncthreads();

    // fp32 transpose out
    for (int i = tid; i < (D/4) * PK; i += THREADS) {
        int dq = i / PK, kl = i % PK;
        float4 v;
        v.x = tile[(4*dq+0)*PK + kl];
        v.y = tile[(4*dq+1)*PK + kl];
        v.z = tile[(4*dq+2)*PK + kl];
        v.w = tile[(4*dq+3)*PK + kl];
        *(float4*)(g_eT + (size_t)(k0 + kl)*D + 4*dq) = v;
    }

    // fragment-ordered bf16: word(t,lane,j) j<8: s=j>>1, half=j&1
    // value = bf16x2( e[n][k], e[n][k+1] ), n_local = tl*8+lane/4,
    // k = s*16 + (lane&3)*2 + half*8
    for (int i = tid; i < 16*384; i += THREADS) {
        int tl   = i / 384;
        int r    = i % 384;
        int lane = r / 12;
        int j    = r % 12;
        uint32_t w = 0;
        if (j < 8) {
            int s = j >> 1, hf = j & 1;
            int nl = tl*8 + (lane >> 2);
            int k  = s*16 + (lane & 3)*2 + hf*8;
            w = packbf2(tile[k*PK + nl], tile[(k+1)*PK + nl]);
        }
        g_frag[(nt*16 + tl)*384 + r] = w;
    }

    // norms: sequential d, separate mul/add (XLA order)
    if (tid < PK) {
        float s = 0.f;
#pragma unroll
        for (int d = 0; d < D; d++) {
            float v = tile[d*PK + tid];
            s = __fadd_rn(s, __fmul_rn(v, v));
        }
        g_en[k0 + tid] = s;
    }
}

// ---------------------------------------------------------------------------
// Main: warp = 16-row stripe. HMMA bf16 scores -> margin prune -> exact fp32
// recheck (reference rounding) -> cooperative gather/MSE output.
// ---------------------------------------------------------------------------
__global__ void __launch_bounds__(THREADS, 2)
vq_main(const float* __restrict__ x, float* __restrict__ dout) {
    extern __shared__ char smem[];
    const int tid  = threadIdx.x;
    const int wid  = tid >> 5;
    const int lane = tid & 31;

    float*  ens = (float*)(smem + OFF_ENS);
    float*  fns = (float*)(smem + OFF_FN);
    int*    bks = (int*)(smem + OFF_BK);
    float*  red = (float*)(smem + OFF_RED);

    // stage fragment codebook (96 KB) + norms
    {
        const uint4* src = (const uint4*)g_frag;
        uint4* dst = (uint4*)(smem + OFF_B);
#pragma unroll
        for (int i = 0; i < 24; i++) dst[tid + i*THREADS] = src[tid + i*THREADS];
        for (int i = tid; i < KCODES; i += THREADS) ens[i] = g_en[i];
    }

    // per-row ||f||^2, XLA sequential rounding
    if (tid < TM) {
        const float4* xr = (const float4*)(x + ((size_t)blockIdx.x*TM + tid)*D);
        float s = 0.f;
#pragma unroll
        for (int q = 0; q < 16; q++) {
            float4 v = __ldg(xr + q);
            s = __fadd_rn(s, __fmul_rn(v.x, v.x));
            s = __fadd_rn(s, __fmul_rn(v.y, v.y));
            s = __fadd_rn(s, __fmul_rn(v.z, v.z));
            s = __fadd_rn(s, __fmul_rn(v.w, v.w));
        }
        fns[tid] = s;
    }

    // A fragments from global (bf16): rows R0 = stripe+lane/4, R1 = R0+8
    const int   rq = lane >> 2;
    const int   kp = (lane & 3) * 2;
    const size_t rowbase = (size_t)blockIdx.x*TM + wid*16;
    const float* xR0 = x + (rowbase + rq)*D;
    const float* xR1 = xR0 + 8*D;

    uint32_t afrag[4][4];
#pragma unroll
    for (int s = 0; s < 4; s++) {
        float2 v;
        v = *(const float2*)(xR0 + s*16 + kp);     afrag[s][0] = packbf2(v.x, v.y);
        v = *(const float2*)(xR1 + s*16 + kp);     afrag[s][1] = packbf2(v.x, v.y);
        v = *(const float2*)(xR0 + s*16 + kp + 8); afrag[s][2] = packbf2(v.x, v.y);
        v = *(const float2*)(xR1 + s*16 + kp + 8); afrag[s][3] = packbf2(v.x, v.y);
    }
    __syncthreads();

    // ---- scan 64 n8-tiles ----
    float gmin0 = 3.4e38f, gmin1 = 3.4e38f;
    int   cnt = 0;
    bool  ovf = false;
    int   kcv[CAP];
    float gcv[CAP];

    const char* bbase = smem + OFF_B + (size_t)lane*48;
    const float2* en2 = (const float2*)ens;

#pragma unroll 4
    for (int t = 0; t < 64; t++) {
        uint4 B0 = *(const uint4*)(bbase + t*1536);
        uint4 B1 = *(const uint4*)(bbase + t*1536 + 16);
        float acc[4] = {0.f, 0.f, 0.f, 0.f};
        mma16816(acc, afrag[0], B0.x, B0.y);
        mma16816(acc, afrag[1], B0.z, B0.w);
        mma16816(acc, afrag[2], B1.x, B1.y);
        mma16816(acc, afrag[3], B1.z, B1.w);

        float2 en = en2[t*4 + (lane & 3)];
        int k0 = t*8 + kp;
        float g0 = fmaf(-2.f, acc[0], en.x);   // (row0, k0)
        float g1 = fmaf(-2.f, acc[1], en.y);   // (row0, k0+1)
        float g2 = fmaf(-2.f, acc[2], en.x);   // (row1, k0)
        float g3 = fmaf(-2.f, acc[3], en.y);   // (row1, k0+1)

        gmin0 = fminf(gmin0, fminf(g0, g1));
        gmin1 = fminf(gmin1, fminf(g2, g3));
        float lim0 = gmin0 + MARGIN, lim1 = gmin1 + MARGIN;

        // candidate inserts (rare)
        if (g0 <= lim0 || g1 <= lim0 || g2 <= lim1 || g3 <= lim1) {
            float gg[4] = {g0, g1, g2, g3};
            int   kk[4] = {k0, k0+1, k0 + 1024, k0 + 1 + 1024}; // bit10 = row1
#pragma unroll
            for (int m = 0; m < 4; m++) {
                float lim = (m < 2) ? lim0 : lim1;
                if (gg[m] <= lim) {
                    if (cnt == CAP) {  // compact: evict stale entries
                        int w = 0;
#pragma unroll
                        for (int i = 0; i < CAP; i++) {
                            float li = (kcv[i] & 1024) ? lim1 : lim0;
                            if (gcv[i] <= li) { kcv[w] = kcv[i]; gcv[w] = gcv[i]; w++; }
                        }
                        cnt = w;
                    }
                    if (cnt < CAP) { kcv[cnt] = kk[m]; gcv[cnt] = gg[m]; cnt++; }
                    else ovf = true;
                }
            }
        }

        if ((t & 7) == 7) {  // quad min refresh (cols are disjoint across quad)
            gmin0 = fminf(gmin0, __shfl_xor_sync(0xffffffffu, gmin0, 1));
            gmin0 = fminf(gmin0, __shfl_xor_sync(0xffffffffu, gmin0, 2));
            gmin1 = fminf(gmin1, __shfl_xor_sync(0xffffffffu, gmin1, 1));
            gmin1 = fminf(gmin1, __shfl_xor_sync(0xffffffffu, gmin1, 2));
        }
    }

    // final limits
    const float lim0 = gmin0 + MARGIN, lim1 = gmin1 + MARGIN;
    const float fn0 = fns[wid*16 + rq], fn1 = fns[wid*16 + rq + 8];

    float bd0 = 3.4e38f, bd1 = 3.4e38f;
    int   bk0 = 1023,    bk1 = 1023;

    if (!ovf) {
#pragma unroll 1
        for (int i = 0; i < cnt; i++) {
            int  kk  = kcv[i];
            int  k   = kk & 511;
            bool r1  = (kk & 1024) != 0;
            float li = r1 ? lim1 : lim0;
            if (gcv[i] <= li) {
                float d = exact_dist(r1 ? xR1 : xR0, g_eT + (size_t)k*D,
                                     r1 ? fn1 : fn0, ens[k]);
                if (r1) { if (d < bd1 || (d == bd1 && k < bk1)) { bd1 = d; bk1 = k; } }
                else    { if (d < bd0 || (d == bd0 && k < bk0)) { bd0 = d; bk0 = k; } }
            }
        }
    } else {
        // ~never: exact full scan, ascending k, both rows
#pragma unroll 1
        for (int k = 0; k < KCODES; k++) {
            const float* e = g_eT + (size_t)k*D;
            float d0 = exact_dist(xR0, e, fn0, ens[k]);
            float d1 = exact_dist(xR1, e, fn1, ens[k]);
            if (d0 < bd0) { bd0 = d0; bk0 = k; }
            if (d1 < bd1) { bd1 = d1; bk1 = k; }
        }
    }

    // quad lexicographic reduce (exact dists; first-index tie-break)
#pragma unroll
    for (int m = 1; m < 4; m <<= 1) {
        float od = __shfl_xor_sync(0xffffffffu, bd0, m);
        int   ok = __shfl_xor_sync(0xffffffffu, bk0, m);
        if (od < bd0 || (od == bd0 && ok < bk0)) { bd0 = od; bk0 = ok; }
        od = __shfl_xor_sync(0xffffffffu, bd1, m);
        ok = __shfl_xor_sync(0xffffffffu, bk1, m);
        if (od < bd1 || (od == bd1 && ok < bk1)) { bd1 = od; bk1 = ok; }
    }
    if ((lane & 3) == 0) {
        bks[wid*16 + rq]     = bk0;
        bks[wid*16 + rq + 8] = bk1;
    }
    __syncthreads();

    // cooperative output: 2048 float4 (gather + MSE), coalesced by row
    float ds = 0.f;
#pragma unroll
    for (int i = 0; i < 8; i++) {
        int idx = tid + i*THREADS;        // 0..2047
        int row = idx >> 4, q = idx & 15;
        size_t grow = (size_t)blockIdx.x*TM + row;
        float4 ev = __ldg((const float4*)(g_eT + (size_t)bks[row]*D) + q);
        float4 xv = __ldg((const float4*)(x + grow*D) + q);
        *((float4*)(dout + grow*D) + q) = ev;
        float a = ev.x - xv.x, b = ev.y - xv.y, c = ev.z - xv.z, d = ev.w - xv.w;
        ds += a*a + b*b + c*c + d*d;
    }
    if (tid < TM)
        dout[IND_OFF + (size_t)blockIdx.x*TM + tid] = (float)bks[tid];

    red[tid] = ds;
    __syncthreads();
#pragma unroll
    for (int s = THREADS/2; s > 0; s >>= 1) {
        if (tid < s) red[tid] += red[tid + s];
        __syncthreads();
    }
    if (tid == 0) g_partial[blockIdx.x] = red[0];
}

// ---------------------------------------------------------------------------
__global__ void vq_fin(float* __restrict__ dout) {
    __shared__ double rd[NBLK];
    int t = threadIdx.x;
    rd[t] = (double)g_partial[t];
    __syncthreads();
#pragma unroll
    for (int s = NBLK/2; s > 0; s >>= 1) {
        if (t < s) rd[t] += rd[t + s];
        __syncthreads();
    }
    if (t == 0) {
        dout[DIFF_OFF] = (float)(rd[0] / (double)OUT_ELEMS);
        float p = 1.0f / 512.0f;   // perplexity is data-independent
        dout[PPL_OFF] = expf(-(p * logf(p + 1e-10f)));
    }
}

// ---------------------------------------------------------------------------
extern "C" void kernel_launch(void* const* d_in, const int* in_sizes, int n_in,
                              void* d_out, int out_size) {
    const float* x     = (const float*)d_in[0];
    const float* embed = (const float*)d_in[1];
    float* dout = (float*)d_out;

    cudaFuncSetAttribute(vq_main, cudaFuncAttributeMaxDynamicSharedMemorySize,
                         SMEM_TOTAL);

    vq_prep<<<KCODES/PK, THREADS>>>(embed);
    vq_main<<<NBLK, THREADS, SMEM_TOTAL>>>(x, dout);
    vq_fin<<<1, NBLK>>>(dout);
}